// round 8
// baseline (speedup 1.0000x reference)
#include <cuda_runtime.h>

#define NPED 4096
#define HALF 2048
#define WPB 8            // 8 warps = 4 rows per block (2 warps per row)
#define THREADS (WPB*32)
#define FULL 0xffffffffu
#define FINF __int_as_float(0x7f800000)
#define SENT 0x7f800000FFFFFFFFULL

typedef unsigned long long u64;

#define PACK2(o, lo, hi) asm("mov.b64 %0, {%1, %2};" : "=l"(o) : "f"(lo), "f"(hi))
#define UNPK2(lo, hi, v) asm("mov.b64 {%0, %1}, %2;" : "=f"(lo), "=f"(hi) : "l"(v))
#define ADD2(o, a, b)    asm("add.rn.f32x2 %0, %1, %2;" : "=l"(o) : "l"(a), "l"(b))
#define MUL2(o, a, b)    asm("mul.rn.f32x2 %0, %1, %2;" : "=l"(o) : "l"(a), "l"(b))

// exact per-element RN, identical to scalar __fadd_rn/__fmul_rn sequence:
// d = fl(fl(dx^2)+fl(dy^2)) + 1 for two candidates packed in one register.
#define DIST2(q, e0, e1) do {                                                  \
    u64 _qx, _qy, _dx, _dy, _xx, _yy, _s, _d;                                  \
    PACK2(_qx, (q).x, (q).z); PACK2(_qy, (q).y, (q).w);                        \
    ADD2(_dx, _qx, npx2);  ADD2(_dy, _qy, npy2);                               \
    MUL2(_xx, _dx, _dx);   MUL2(_yy, _dy, _dy);                                \
    ADD2(_s, _xx, _yy);    ADD2(_d, _s, one2);                                 \
    UNPK2(e0, e1, _d);                                                         \
} while (0)

// insert key into replicated sorted top-4 m0<=m1<=m2<=m3 (warp-uniform)
#define KINSERT(_k) do {                                                       \
    if (_k < m3) {                                                             \
        if (_k < m2) {                                                         \
            m3 = m2;                                                           \
            if (_k < m1) {                                                     \
                m2 = m1;                                                       \
                if (_k < m0) { m1 = m0; m0 = _k; } else m1 = _k;               \
            } else m2 = _k;                                                    \
        } else m3 = _k;                                                        \
    }                                                                          \
} while (0)

#define INSERT(d2v, jv) do {                                                   \
    u64 _k = ((u64)__float_as_uint(d2v) << 32) | (unsigned)(jv);               \
    KINSERT(_k);                                                               \
    tau = fminf(tau, __uint_as_float((unsigned)(m3 >> 32)));                   \
} while (0)

#define SLOWPATH(jbase) do {                                                   \
    while (bal) {                                                              \
        const int r = __ffs(bal) - 1;                                          \
        bal &= bal - 1;                                                        \
        float b0 = __shfl_sync(FULL, a0, r);                                   \
        float b1 = __shfl_sync(FULL, a1, r);                                   \
        float b2 = __shfl_sync(FULL, a2, r);                                   \
        float b3 = __shfl_sync(FULL, a3, r);                                   \
        float b4 = __shfl_sync(FULL, a4, r);                                   \
        float b5 = __shfl_sync(FULL, a5, r);                                   \
        float b6 = __shfl_sync(FULL, a6, r);                                   \
        float b7 = __shfl_sync(FULL, a7, r);                                   \
        const int jb = (jbase) + 2 * r;                                        \
        if (b0 <= tau && jb       != i) INSERT(b0, jb);                        \
        if (b1 <= tau && jb + 1   != i) INSERT(b1, jb + 1);                    \
        if (b2 <= tau && jb + 64  != i) INSERT(b2, jb + 64);                   \
        if (b3 <= tau && jb + 65  != i) INSERT(b3, jb + 65);                   \
        if (b4 <= tau && jb + 128 != i) INSERT(b4, jb + 128);                  \
        if (b5 <= tau && jb + 129 != i) INSERT(b5, jb + 129);                  \
        if (b6 <= tau && jb + 192 != i) INSERT(b6, jb + 192);                  \
        if (b7 <= tau && jb + 193 != i) INSERT(b7, jb + 193);                  \
    }                                                                          \
} while (0)

#define LOADCALC(pbase) do {                                                   \
    float4 q0 = spos4[(pbase)];                                                \
    float4 q1 = spos4[(pbase) + 32];                                           \
    float4 q2 = spos4[(pbase) + 64];                                           \
    float4 q3 = spos4[(pbase) + 96];                                           \
    DIST2(q0, a0, a1); DIST2(q1, a2, a3);                                      \
    DIST2(q2, a4, a5); DIST2(q3, a6, a7);                                      \
    dmin = fminf(fminf(fminf(a0, a1), fminf(a2, a3)),                          \
                 fminf(fminf(a4, a5), fminf(a6, a7)));                         \
} while (0)

__global__ __launch_bounds__(THREADS, 1)
void nn_tag_pool_kernel(const float2* __restrict__ obs1,
                        const float2* __restrict__ obs2,
                        const float*  __restrict__ W,
                        const float*  __restrict__ bias,
                        float* __restrict__ out, int n)
{
    __shared__ float4 spos4[NPED / 2];
    __shared__ u64 smerge[WPB][4];
    const float2* spos2 = (const float2*)spos4;

    const float4* o2v = (const float4*)obs2;
    for (int t = threadIdx.x; t < NPED / 2; t += THREADS) spos4[t] = o2v[t];
    __syncthreads();

    const int lane = threadIdx.x & 31;
    const int wid  = threadIdx.x >> 5;
    const int half = wid & 1;                         // which candidate half
    const int i    = blockIdx.x * (WPB / 2) + (wid >> 1);   // row

    const float2 pi = spos2[i];
    const float npx = -pi.x, npy = -pi.y;
    u64 npx2, npy2, one2;
    PACK2(npx2, npx, npx); PACK2(npy2, npy, npy); PACK2(one2, 1.0f, 1.0f);

    u64 m0 = SENT, m1 = SENT, m2 = SENT, m3 = SENT;
    float a0, a1, a2, a3, a4, a5, a6, a7, dmin;

    const int pbase0 = half * (HALF / 2) + lane;      // float4 index base
    const int jbase0 = half * HALF;

    // ---- iteration 0 of this half: compute, seed tau, process ----
    LOADCALC(pbase0);

    // tau seed = 5th smallest of the 32 lane minima of the first 256
    // candidates of this half: >= 4th-smallest non-self distance in the
    // half (subset order stats + 1 slot of self slack); duplicate collapse
    // only loosens it. Valid gate: nothing in the half's top-4 is rejected.
    float tau;
    {
        float v = dmin;
        #pragma unroll
        for (int k = 0; k < 5; k++) {
            float mn = v;
            #pragma unroll
            for (int off = 16; off; off >>= 1)
                mn = fminf(mn, __shfl_xor_sync(FULL, mn, off));
            tau = mn;
            if (v == mn) v = FINF;
        }
    }

    unsigned bal = __ballot_sync(FULL, dmin <= tau);
    if (bal) SLOWPATH(jbase0);

    // ---- iterations 1..7 over this warp's half ----
    #pragma unroll 7
    for (int it = 1; it < HALF / 256; ++it) {
        LOADCALC(pbase0 + it * 128);
        bal = __ballot_sync(FULL, dmin <= tau);
        if (bal) SLOWPATH(jbase0 + it * 256);
    }

    // ---- cross-warp merge: partner warp (wid^1) scanned the other half ----
    if (lane < 4)
        smerge[wid][lane] = (lane == 0) ? m0 : (lane == 1) ? m1
                          : (lane == 2) ? m2 : m3;
    __syncthreads();

    if (half) return;                 // odd warps done; even warp finishes row

    {
        const int pw = wid ^ 1;
        u64 p0 = smerge[pw][0], p1 = smerge[pw][1];
        u64 p2 = smerge[pw][2], p3 = smerge[pw][3];
        KINSERT(p0); KINSERT(p1); KINSERT(p2); KINSERT(p3);
    }

    // m0..m3 = exact (dist2, index)-lexicographic top-4 of row i.
    // Epilogue: lane = nb*8 + o covers 4 neighbors x 8 outputs.
    const int nb = lane >> 3;
    const int o  = lane & 7;
    u64 sel = (nb == 0) ? m0 : (nb == 1) ? m1 : (nb == 2) ? m2 : m3;
    const int j = (int)(unsigned)sel;

    float2 pj  = spos2[j];
    float2 o1j = obs1[j];
    float2 o1i = obs1[i];

    float px = pj.x - pi.x;
    float py = pj.y - pi.y;
    float vx = (pj.x - o1j.x) - (pi.x - o1i.x);
    float vy = (pj.y - o1j.y) - (pi.y - o1i.y);

    const float* w = W + o * 6;
    float acc = bias[o] + w[2] + w[5];     // both tag features are 1.0
    acc = fmaf(w[0], px, acc);
    acc = fmaf(w[1], py, acc);
    acc = fmaf(w[3], vx, acc);
    acc = fmaf(w[4], vy, acc);
    out[i * 32 + lane] = fmaxf(acc, 0.0f);
}

extern "C" void kernel_launch(void* const* d_in, const int* in_sizes, int n_in,
                              void* d_out, int out_size)
{
    const float2* obs1 = (const float2*)d_in[0];
    const float2* obs2 = (const float2*)d_in[1];
    const float*  W    = (const float*)d_in[2];
    const float*  bias = (const float*)d_in[3];
    float* out = (float*)d_out;

    int n = in_sizes[0] / 2;                       // obs1 is [n,2]
    int rows_per_block = WPB / 2;
    int grid = (n + rows_per_block - 1) / rows_per_block;
    nn_tag_pool_kernel<<<grid, THREADS>>>(obs1, obs2, W, bias, out, n);
}

// round 10
// speedup vs baseline: 1.2913x; 1.2913x over previous
#include <cuda_runtime.h>

#define NPED 4096
#define HALF 2048
#define WPB 16           // 16 warps = 8 rows per block (2 warps per row)
#define THREADS (WPB*32)
#define FULL 0xffffffffu
#define FINF __int_as_float(0x7f800000)
#define SENT 0x7f800000FFFFFFFFULL

typedef unsigned long long u64;

// exact reference rounding: fl(fl(dx^2)+fl(dy^2)) + 1, no FMA contraction
#define DIST(qx, qy, dd) do {                                                  \
    float _dx = __fadd_rn((qx), npx), _dy = __fadd_rn((qy), npy);              \
    dd = __fadd_rn(__fadd_rn(__fmul_rn(_dx,_dx), __fmul_rn(_dy,_dy)), 1.0f);   \
} while (0)

// insert key into replicated sorted top-4 m0<=m1<=m2<=m3 (warp-uniform)
#define KINSERT(_k) do {                                                       \
    if (_k < m3) {                                                             \
        if (_k < m2) {                                                         \
            m3 = m2;                                                           \
            if (_k < m1) {                                                     \
                m2 = m1;                                                       \
                if (_k < m0) { m1 = m0; m0 = _k; } else m1 = _k;               \
            } else m2 = _k;                                                    \
        } else m3 = _k;                                                        \
    }                                                                          \
} while (0)

#define INSERT(d2v, jv) do {                                                   \
    u64 _k = ((u64)__float_as_uint(d2v) << 32) | (unsigned)(jv);               \
    KINSERT(_k);                                                               \
    tau = fminf(tau, __uint_as_float((unsigned)(m3 >> 32)));                   \
} while (0)

#define SLOWPATH(jbase) do {                                                   \
    while (bal) {                                                              \
        const int r = __ffs(bal) - 1;                                          \
        bal &= bal - 1;                                                        \
        float b0 = __shfl_sync(FULL, a0, r);                                   \
        float b1 = __shfl_sync(FULL, a1, r);                                   \
        float b2 = __shfl_sync(FULL, a2, r);                                   \
        float b3 = __shfl_sync(FULL, a3, r);                                   \
        float b4 = __shfl_sync(FULL, a4, r);                                   \
        float b5 = __shfl_sync(FULL, a5, r);                                   \
        float b6 = __shfl_sync(FULL, a6, r);                                   \
        float b7 = __shfl_sync(FULL, a7, r);                                   \
        const int jb = (jbase) + 2 * r;                                        \
        if (b0 <= tau && jb       != i) INSERT(b0, jb);                        \
        if (b1 <= tau && jb + 1   != i) INSERT(b1, jb + 1);                    \
        if (b2 <= tau && jb + 64  != i) INSERT(b2, jb + 64);                   \
        if (b3 <= tau && jb + 65  != i) INSERT(b3, jb + 65);                   \
        if (b4 <= tau && jb + 128 != i) INSERT(b4, jb + 128);                  \
        if (b5 <= tau && jb + 129 != i) INSERT(b5, jb + 129);                  \
        if (b6 <= tau && jb + 192 != i) INSERT(b6, jb + 192);                  \
        if (b7 <= tau && jb + 193 != i) INSERT(b7, jb + 193);                  \
    }                                                                          \
} while (0)

#define LOADCALC(pbase) do {                                                   \
    float4 q0 = spos4[(pbase)];                                                \
    float4 q1 = spos4[(pbase) + 32];                                           \
    float4 q2 = spos4[(pbase) + 64];                                           \
    float4 q3 = spos4[(pbase) + 96];                                           \
    DIST(q0.x, q0.y, a0); DIST(q0.z, q0.w, a1);                                \
    DIST(q1.x, q1.y, a2); DIST(q1.z, q1.w, a3);                                \
    DIST(q2.x, q2.y, a4); DIST(q2.z, q2.w, a5);                                \
    DIST(q3.x, q3.y, a6); DIST(q3.z, q3.w, a7);                                \
    dmin = fminf(fminf(fminf(a0, a1), fminf(a2, a3)),                          \
                 fminf(fminf(a4, a5), fminf(a6, a7)));                         \
} while (0)

__global__ __launch_bounds__(THREADS, 2)
void nn_tag_pool_kernel(const float2* __restrict__ obs1,
                        const float2* __restrict__ obs2,
                        const float*  __restrict__ W,
                        const float*  __restrict__ bias,
                        float* __restrict__ out, int n)
{
    __shared__ float4 spos4[NPED / 2];
    __shared__ u64 smerge[WPB][4];
    const float2* spos2 = (const float2*)spos4;

    const float4* o2v = (const float4*)obs2;
    for (int t = threadIdx.x; t < NPED / 2; t += THREADS) spos4[t] = o2v[t];
    __syncthreads();

    const int lane = threadIdx.x & 31;
    const int wid  = threadIdx.x >> 5;
    const int half = wid & 1;                              // candidate half
    const int i    = blockIdx.x * (WPB / 2) + (wid >> 1);  // row

    const float2 pi = spos2[i];
    const float npx = -pi.x, npy = -pi.y;

    u64 m0 = SENT, m1 = SENT, m2 = SENT, m3 = SENT;
    float a0, a1, a2, a3, a4, a5, a6, a7, dmin;

    const int pbase0 = half * (HALF / 2) + lane;   // float4 index base
    const int jbase0 = half * HALF;

    // ---- iteration 0 of this half: compute, seed tau, process ----
    LOADCALC(pbase0);

    // tau seed = 5th smallest of the 32 lane minima of the first 256
    // candidates of this half: >= 4th-smallest non-self distance in the half
    // (subset order stats + one slot of self slack); duplicate collapse only
    // loosens it. Nothing belonging to the half's exact top-4 is rejected.
    float tau;
    {
        float v = dmin;
        #pragma unroll
        for (int k = 0; k < 5; k++) {
            float mn = v;
            #pragma unroll
            for (int off = 16; off; off >>= 1)
                mn = fminf(mn, __shfl_xor_sync(FULL, mn, off));
            tau = mn;
            if (v == mn) v = FINF;
        }
    }

    unsigned bal = __ballot_sync(FULL, dmin <= tau);
    if (bal) SLOWPATH(jbase0);

    // ---- iterations 1..7 over this warp's half ----
    #pragma unroll 4
    for (int it = 1; it < HALF / 256; ++it) {
        LOADCALC(pbase0 + it * 128);
        bal = __ballot_sync(FULL, dmin <= tau);
        if (bal) SLOWPATH(jbase0 + it * 256);
    }

    // ---- cross-warp merge: partner warp (wid^1) scanned the other half ----
    if (lane < 4)
        smerge[wid][lane] = (lane == 0) ? m0 : (lane == 1) ? m1
                          : (lane == 2) ? m2 : m3;
    __syncthreads();

    if (half) return;               // odd warps done; even warp finishes row

    {
        const int pw = wid ^ 1;
        u64 p0 = smerge[pw][0], p1 = smerge[pw][1];
        u64 p2 = smerge[pw][2], p3 = smerge[pw][3];
        KINSERT(p0); KINSERT(p1); KINSERT(p2); KINSERT(p3);
    }

    // m0..m3 = exact (dist2, index)-lexicographic top-4 of row i.
    // Epilogue: lane = nb*8 + o covers 4 neighbors x 8 outputs.
    const int nb = lane >> 3;
    const int o  = lane & 7;
    u64 sel = (nb == 0) ? m0 : (nb == 1) ? m1 : (nb == 2) ? m2 : m3;
    const int j = (int)(unsigned)sel;

    float2 pj  = spos2[j];
    float2 o1j = obs1[j];
    float2 o1i = obs1[i];

    float px = pj.x - pi.x;
    float py = pj.y - pi.y;
    float vx = (pj.x - o1j.x) - (pi.x - o1i.x);
    float vy = (pj.y - o1j.y) - (pi.y - o1i.y);

    const float* w = W + o * 6;
    float acc = bias[o] + w[2] + w[5];     // both tag features are 1.0
    acc = fmaf(w[0], px, acc);
    acc = fmaf(w[1], py, acc);
    acc = fmaf(w[3], vx, acc);
    acc = fmaf(w[4], vy, acc);
    out[i * 32 + lane] = fmaxf(acc, 0.0f);
}

extern "C" void kernel_launch(void* const* d_in, const int* in_sizes, int n_in,
                              void* d_out, int out_size)
{
    const float2* obs1 = (const float2*)d_in[0];
    const float2* obs2 = (const float2*)d_in[1];
    const float*  W    = (const float*)d_in[2];
    const float*  bias = (const float*)d_in[3];
    float* out = (float*)d_out;

    int n = in_sizes[0] / 2;                       // obs1 is [n,2]
    int rows_per_block = WPB / 2;
    int grid = (n + rows_per_block - 1) / rows_per_block;
    nn_tag_pool_kernel<<<grid, THREADS>>>(obs1, obs2, W, bias, out, n);
}